// round 2
// baseline (speedup 1.0000x reference)
#include <cuda_runtime.h>
#include <math.h>

#define BB 16
#define TT 2048
#define DD 1024
#define CC 6

// ---------------- device scratch (no allocs allowed) ----------------
__device__ int   g_is64;
__device__ int   g_tok[BB * TT];
__device__ float g_q[BB * DD];
__device__ float g_qk[BB * DD];
__device__ float g_scores[BB * TT];
__device__ float g_xw[BB * DD];
__device__ float g_tmp[BB * DD];
__device__ float g_tmp2[BB * DD];
__device__ float g_inv1[BB];

__device__ __forceinline__ float warp_sum(float v) {
#pragma unroll
    for (int o = 16; o > 0; o >>= 1) v += __shfl_down_sync(0xffffffffu, v, o);
    return v;
}

// ---------------- K0: detect int32 vs int64 token layout ----------------
__global__ void k_detect(const int2* text2, int V) {
    __shared__ int ok;
    if (threadIdx.x == 0) ok = 1;
    __syncthreads();
    // Check first 4096 int64-slots (32KB — safe for both layouts).
    // Genuine int64 tokens: low word in [0,V), high word 0.
    for (int i = threadIdx.x; i < 4096; i += blockDim.x) {
        int2 v = text2[i];
        if (v.y != 0 || v.x < 0 || v.x >= V) ok = 0;
    }
    __syncthreads();
    if (threadIdx.x == 0) g_is64 = ok;
}

// ---------------- K1: convert tokens; zero g_qk ----------------
__global__ void k_convert(const void* text) {
    int i = blockIdx.x * blockDim.x + threadIdx.x;
    if (i < BB * TT) {
        int t;
        if (g_is64) t = (int)((const long long*)text)[i];
        else        t = ((const int*)text)[i];
        g_tok[i] = t;
    }
    if (i < BB * DD) g_qk[i] = 0.0f;
}

// ---------------- K2a: q[b] = Wq @ xlast[b] + bq  (grid = D) ----------------
__global__ void k_q(const float* __restrict__ emb, const float* __restrict__ Wq,
                    const float* __restrict__ bq) {
    int d = blockIdx.x, t = threadIdx.x;        // 256 threads
    float4 w4 = ((const float4*)(Wq + (size_t)d * DD))[t];
    float acc[BB];
#pragma unroll
    for (int b = 0; b < BB; b++) {
        int row = g_tok[(b + 1) * TT - 1];
        float4 x = ((const float4*)(emb + (size_t)row * DD))[t];
        acc[b] = w4.x * x.x + w4.y * x.y + w4.z * x.z + w4.w * x.w;
    }
    __shared__ float red[BB][9];
    int lane = t & 31, wid = t >> 5;
#pragma unroll
    for (int b = 0; b < BB; b++) {
        float r = warp_sum(acc[b]);
        if (lane == 0) red[b][wid] = r;
    }
    __syncthreads();
    if (t < BB) {
        float s = 0.f;
#pragma unroll
        for (int w = 0; w < 8; w++) s += red[t][w];
        g_q[t * DD + d] = s + bq[d];
    }
}

// ---------------- K2b: qk[b][j] += sum_d q[b][d] * Wk[d][j] ----------------
__global__ void k_qk(const float* __restrict__ Wk) {
    int j  = blockIdx.x * 256 + threadIdx.x;   // grid (4, 8)
    int d0 = blockIdx.y * 128;
    __shared__ float shq[BB * 128];
    for (int i = threadIdx.x; i < BB * 128; i += 256) {
        int b = i >> 7, dd = i & 127;
        shq[i] = g_q[b * DD + d0 + dd];
    }
    __syncthreads();
    float acc[BB];
#pragma unroll
    for (int b = 0; b < BB; b++) acc[b] = 0.f;
    for (int dd = 0; dd < 128; dd++) {
        float w = Wk[(size_t)(d0 + dd) * DD + j];
#pragma unroll
        for (int b = 0; b < BB; b++) acc[b] += shq[b * 128 + dd] * w;
    }
#pragma unroll
    for (int b = 0; b < BB; b++) atomicAdd(&g_qk[b * DD + j], acc[b]);
}

// ---------------- K3: scores[i] = dot(qk[b], emb[tok[i]]) / sqrt(D) ----------------
__global__ void k_scores(const float* __restrict__ emb, float scale) {
    int wid = threadIdx.x >> 5, lane = threadIdx.x & 31;
    int i = blockIdx.x * 8 + wid;              // global token index; 4096 blocks x 8 warps
    int b = i >> 11;                           // uniform per block (8 | 2048)
    __shared__ float4 shqk[256];
    shqk[threadIdx.x] = ((const float4*)(g_qk + b * DD))[threadIdx.x];
    __syncthreads();
    int row = g_tok[i];
    const float4* e4 = (const float4*)(emb + (size_t)row * DD);
    float acc = 0.f;
#pragma unroll
    for (int it = 0; it < 8; it++) {
        float4 e = e4[it * 32 + lane];
        float4 q = shqk[it * 32 + lane];
        acc += e.x * q.x + e.y * q.y + e.z * q.z + e.w * q.w;
    }
    acc = warp_sum(acc);
    if (lane == 0) g_scores[i] = acc * scale;
}

// ---------------- K4: per-batch softmax over T; zero g_xw ----------------
__global__ void k_softmax() {
    int b = blockIdx.x, t = threadIdx.x;       // 256 threads
    __shared__ float sh[256];
    float v[8];
    float m = -1e30f;
#pragma unroll
    for (int k = 0; k < 8; k++) { v[k] = g_scores[b * TT + k * 256 + t]; m = fmaxf(m, v[k]); }
    sh[t] = m; __syncthreads();
    for (int s = 128; s > 0; s >>= 1) { if (t < s) sh[t] = fmaxf(sh[t], sh[t + s]); __syncthreads(); }
    m = sh[0]; __syncthreads();
    float l = 0.f;
#pragma unroll
    for (int k = 0; k < 8; k++) { v[k] = __expf(v[k] - m); l += v[k]; }
    sh[t] = l; __syncthreads();
    for (int s = 128; s > 0; s >>= 1) { if (t < s) sh[t] += sh[t + s]; __syncthreads(); }
    float winv = 1.0f / sh[0];
#pragma unroll
    for (int k = 0; k < 8; k++) g_scores[b * TT + k * 256 + t] = v[k] * winv;
#pragma unroll
    for (int k = 0; k < 4; k++) g_xw[b * DD + k * 256 + t] = 0.0f;
}

// ---------------- K5: xw[b] = sum_j w_j * emb[tok[b,j]] ----------------
__global__ void k_wsum(const float* __restrict__ emb) {
    int b = blockIdx.y, c = blockIdx.x;        // grid (32, 16), 64 tokens per block
    int t = threadIdx.x;                       // 256 threads, each owns a float4
    int j0 = c * 64;
    float4 acc = make_float4(0.f, 0.f, 0.f, 0.f);
#pragma unroll 4
    for (int jj = 0; jj < 64; jj++) {
        int j = j0 + jj;
        int   row = g_tok[b * TT + j];
        float w   = g_scores[b * TT + j];
        float4 e = ((const float4*)(emb + (size_t)row * DD))[t];
        acc.x += w * e.x; acc.y += w * e.y; acc.z += w * e.z; acc.w += w * e.w;
    }
    float* out = g_xw + b * DD + t * 4;
    atomicAdd(out + 0, acc.x); atomicAdd(out + 1, acc.y);
    atomicAdd(out + 2, acc.z); atomicAdd(out + 3, acc.w);
}

// ---------------- K6: tmp[b] = Wv @ xw[b] + bv + xlast[b]  (grid = D) ----------------
__global__ void k_v(const float* __restrict__ emb, const float* __restrict__ Wv,
                    const float* __restrict__ bv) {
    int d = blockIdx.x, t = threadIdx.x;
    float4 w4 = ((const float4*)(Wv + (size_t)d * DD))[t];
    float acc[BB];
#pragma unroll
    for (int b = 0; b < BB; b++) {
        float4 x = ((const float4*)(g_xw + b * DD))[t];
        acc[b] = w4.x * x.x + w4.y * x.y + w4.z * x.z + w4.w * x.w;
    }
    __shared__ float red[BB][9];
    int lane = t & 31, wid = t >> 5;
#pragma unroll
    for (int b = 0; b < BB; b++) {
        float r = warp_sum(acc[b]);
        if (lane == 0) red[b][wid] = r;
    }
    __syncthreads();
    if (t < BB) {
        float s = 0.f;
#pragma unroll
        for (int w = 0; w < 8; w++) s += red[t][w];
        int row = g_tok[(t + 1) * TT - 1];
        g_tmp[t * DD + d] = s + bv[d] + emb[(size_t)row * DD + d];
    }
}

// ---------------- K7: inv1[b] = 1/max(||tmp[b]||, eps) ----------------
__global__ void k_norm1() {
    int b = blockIdx.x, t = threadIdx.x;       // 256 threads
    float4 v = ((const float4*)(g_tmp + b * DD))[t];
    float ss = v.x * v.x + v.y * v.y + v.z * v.z + v.w * v.w;
    __shared__ float sh[256];
    sh[t] = ss; __syncthreads();
    for (int s = 128; s > 0; s >>= 1) { if (t < s) sh[t] += sh[t + s]; __syncthreads(); }
    if (t == 0) g_inv1[b] = 1.0f / fmaxf(sqrtf(sh[0]), 1e-12f);
}

// ---------------- K8: tmp2[b] = y + Wfc @ y + bfc,  y = tmp[b]*inv1[b] ----------------
__global__ void k_fc(const float* __restrict__ Wfc, const float* __restrict__ bfc) {
    int d = blockIdx.x, t = threadIdx.x;
    float4 w4 = ((const float4*)(Wfc + (size_t)d * DD))[t];
    float acc[BB];
#pragma unroll
    for (int b = 0; b < BB; b++) {
        float4 x = ((const float4*)(g_tmp + b * DD))[t];
        acc[b] = w4.x * x.x + w4.y * x.y + w4.z * x.z + w4.w * x.w;
    }
    __shared__ float red[BB][9];
    int lane = t & 31, wid = t >> 5;
#pragma unroll
    for (int b = 0; b < BB; b++) {
        float r = warp_sum(acc[b]);
        if (lane == 0) red[b][wid] = r;
    }
    __syncthreads();
    if (t < BB) {
        float s = 0.f;
#pragma unroll
        for (int w = 0; w < 8; w++) s += red[t][w];
        float inv = g_inv1[t];
        g_tmp2[t * DD + d] = (g_tmp[t * DD + d] + s) * inv + bfc[d];
    }
}

// ---------------- K9: l2norm + sigmoid(Wo @ z + bo) ----------------
__global__ void k_out(const float* __restrict__ Wo, const float* __restrict__ bo,
                      float* __restrict__ out) {
    int b = blockIdx.x, t = threadIdx.x;       // 256 threads
    float4 v = ((const float4*)(g_tmp2 + b * DD))[t];
    float ss = v.x * v.x + v.y * v.y + v.z * v.z + v.w * v.w;
    __shared__ float sh[256];
    __shared__ float inv2;
    sh[t] = ss; __syncthreads();
    for (int s = 128; s > 0; s >>= 1) { if (t < s) sh[t] += sh[t + s]; __syncthreads(); }
    if (t == 0) inv2 = 1.0f / fmaxf(sqrtf(sh[0]), 1e-12f);
    __syncthreads();
    int wid = t >> 5, lane = t & 31;
    if (wid < CC) {
        float a = 0.f;
        for (int k = lane; k < DD; k += 32)
            a += Wo[wid * DD + k] * g_tmp2[b * DD + k];
        a = warp_sum(a);
        if (lane == 0) {
            float logit = a * inv2 + bo[wid];
            out[b * CC + wid] = 1.0f / (1.0f + expf(-logit));
        }
    }
}

// ---------------- launch ----------------
extern "C" void kernel_launch(void* const* d_in, const int* in_sizes, int n_in,
                              void* d_out, int out_size) {
    const void*  text = d_in[0];
    const float* emb  = (const float*)d_in[2];
    const float* Wq   = (const float*)d_in[3];
    const float* bq   = (const float*)d_in[4];
    const float* Wk   = (const float*)d_in[5];
    const float* Wv   = (const float*)d_in[7];
    const float* bv   = (const float*)d_in[8];
    const float* Wfc  = (const float*)d_in[9];
    const float* bfc  = (const float*)d_in[10];
    const float* Wo   = (const float*)d_in[11];
    const float* bo   = (const float*)d_in[12];
    int V = in_sizes[2] / DD;

    k_detect<<<1, 256>>>((const int2*)text, V);
    k_convert<<<(BB * TT + 255) / 256, 256>>>(text);
    k_q<<<DD, 256>>>(emb, Wq, bq);
    dim3 gqk(4, 8);
    k_qk<<<gqk, 256>>>(Wk);
    k_scores<<<(BB * TT) / 8, 256>>>(emb, 1.0f / 32.0f);
    k_softmax<<<BB, 256>>>();
    dim3 gws(32, BB);
    k_wsum<<<gws, 256>>>(emb);
    k_v<<<DD, 256>>>(emb, Wv, bv);
    k_norm1<<<BB, 256>>>();
    k_fc<<<DD, 256>>>(Wfc, bfc);
    k_out<<<BB, 256>>>(Wo, bo, (float*)d_out);
}

// round 3
// speedup vs baseline: 1.4548x; 1.4548x over previous
#include <cuda_runtime.h>
#include <math.h>

#define BB 16
#define TT 2048
#define DD 1024
#define CC 6
#define NPART 128   // partials per batch in fused attention

// ---------------- device scratch (no allocs allowed) ----------------
__device__ int   g_is64;
__device__ int   g_tok[BB * TT];
__device__ float g_q[BB * DD];
__device__ float g_qk[BB * DD];
__device__ float g_xw[BB * DD];
__device__ float g_tmp[BB * DD];
__device__ float g_tmp2[BB * DD];
__device__ float g_inv1[BB];
__device__ float g_pm[BB * NPART];
__device__ float g_pl[BB * NPART];
__device__ float g_pacc[BB * NPART * DD];   // 8 MB partial weighted sums

__device__ __forceinline__ float warp_sum(float v) {
#pragma unroll
    for (int o = 16; o > 0; o >>= 1) v += __shfl_down_sync(0xffffffffu, v, o);
    return v;
}
__device__ __forceinline__ float warp_allsum(float v) {
#pragma unroll
    for (int o = 16; o > 0; o >>= 1) v += __shfl_xor_sync(0xffffffffu, v, o);
    return v;
}

// ---------------- K0: detect int32 vs int64 token layout ----------------
__global__ void k_detect(const int2* text2, int V) {
    __shared__ int ok;
    if (threadIdx.x == 0) ok = 1;
    __syncthreads();
    for (int i = threadIdx.x; i < 4096; i += blockDim.x) {
        int2 v = text2[i];
        if (v.y != 0 || v.x < 0 || v.x >= V) ok = 0;
    }
    __syncthreads();
    if (threadIdx.x == 0) g_is64 = ok;
}

// ---------------- K1: convert tokens; zero g_qk ----------------
__global__ void k_convert(const void* text) {
    int i = blockIdx.x * blockDim.x + threadIdx.x;
    if (i < BB * TT) {
        int t;
        if (g_is64) t = (int)((const long long*)text)[i];
        else        t = ((const int*)text)[i];
        g_tok[i] = t;
    }
    if (i < BB * DD) g_qk[i] = 0.0f;
}

// ---------------- K2a: q[b] = Wq @ xlast[b] + bq  (grid = D) ----------------
__global__ void k_q(const float* __restrict__ emb, const float* __restrict__ Wq,
                    const float* __restrict__ bq) {
    int d = blockIdx.x, t = threadIdx.x;        // 256 threads
    float4 w4 = ((const float4*)(Wq + (size_t)d * DD))[t];
    float acc[BB];
#pragma unroll
    for (int b = 0; b < BB; b++) {
        int row = g_tok[(b + 1) * TT - 1];
        float4 x = ((const float4*)(emb + (size_t)row * DD))[t];
        acc[b] = w4.x * x.x + w4.y * x.y + w4.z * x.z + w4.w * x.w;
    }
    __shared__ float red[BB][9];
    int lane = t & 31, wid = t >> 5;
#pragma unroll
    for (int b = 0; b < BB; b++) {
        float r = warp_sum(acc[b]);
        if (lane == 0) red[b][wid] = r;
    }
    __syncthreads();
    if (t < BB) {
        float s = 0.f;
#pragma unroll
        for (int w = 0; w < 8; w++) s += red[t][w];
        g_q[t * DD + d] = s + bq[d];
    }
}

// ---------------- K2b: qk[b][j] += sum_d q[b][d] * Wk[d][j]  (grid (4,32)) ----------------
__global__ void k_qk(const float* __restrict__ Wk) {
    int j  = blockIdx.x * 256 + threadIdx.x;
    int d0 = blockIdx.y * 32;
    __shared__ float shq[BB * 32];
    for (int i = threadIdx.x; i < BB * 32; i += 256) {
        int b = i >> 5, dd = i & 31;
        shq[i] = g_q[b * DD + d0 + dd];
    }
    __syncthreads();
    float acc[BB];
#pragma unroll
    for (int b = 0; b < BB; b++) acc[b] = 0.f;
#pragma unroll
    for (int dd = 0; dd < 32; dd++) {
        float w = Wk[(size_t)(d0 + dd) * DD + j];
#pragma unroll
        for (int b = 0; b < BB; b++) acc[b] += shq[b * 32 + dd] * w;
    }
#pragma unroll
    for (int b = 0; b < BB; b++) atomicAdd(&g_qk[b * DD + j], acc[b]);
}

// ---------------- K3: fused scores+softmax+wsum, single pass over emb rows -----
// grid (16, BB), 256 threads (8 warps). Each warp = one partial (16 tokens).
__global__ void k_attn(const float* __restrict__ emb, float scale) {
    int b = blockIdx.y;
    int wid = threadIdx.x >> 5, lane = threadIdx.x & 31;
    int p = blockIdx.x * 8 + wid;               // partial index 0..127
    __shared__ float4 shqk[256];
    shqk[threadIdx.x] = ((const float4*)(g_qk + b * DD))[threadIdx.x];
    __syncthreads();
    float4 qv[8];
#pragma unroll
    for (int it = 0; it < 8; it++) qv[it] = shqk[it * 32 + lane];

    float m = -1e30f, l = 0.f;
    float4 acc[8];
#pragma unroll
    for (int it = 0; it < 8; it++) acc[it] = make_float4(0.f, 0.f, 0.f, 0.f);

    int j0 = b * TT + p * 16;
#pragma unroll 2
    for (int jj = 0; jj < 16; jj++) {
        int row = g_tok[j0 + jj];
        const float4* e4 = (const float4*)(emb + (size_t)row * DD);
        float4 e[8];
#pragma unroll
        for (int it = 0; it < 8; it++) e[it] = e4[it * 32 + lane];
        float dot = 0.f;
#pragma unroll
        for (int it = 0; it < 8; it++)
            dot += e[it].x * qv[it].x + e[it].y * qv[it].y
                 + e[it].z * qv[it].z + e[it].w * qv[it].w;
        dot = warp_allsum(dot);
        float s  = dot * scale;
        float nm = fmaxf(m, s);
        float f  = __expf(m - nm);
        float pw = __expf(s - nm);
        l = l * f + pw;
#pragma unroll
        for (int it = 0; it < 8; it++) {
            acc[it].x = acc[it].x * f + pw * e[it].x;
            acc[it].y = acc[it].y * f + pw * e[it].y;
            acc[it].z = acc[it].z * f + pw * e[it].z;
            acc[it].w = acc[it].w * f + pw * e[it].w;
        }
        m = nm;
    }
    if (lane == 0) { g_pm[b * NPART + p] = m; g_pl[b * NPART + p] = l; }
    float4* pa = (float4*)(g_pacc + ((size_t)(b * NPART + p)) * DD);
#pragma unroll
    for (int it = 0; it < 8; it++) pa[it * 32 + lane] = acc[it];
}

// ---------------- K4: combine partials -> g_xw  (grid = BB, 256 thr) ----------------
__global__ void k_attn2() {
    int b = blockIdx.x, t = threadIdx.x;
    __shared__ float sred[NPART];
    __shared__ float sw[NPART];
    __shared__ float M, Linv;
    // global max
    if (t < NPART) sred[t] = g_pm[b * NPART + t];
    __syncthreads();
    for (int s = 64; s > 0; s >>= 1) {
        if (t < s) sred[t] = fmaxf(sred[t], sred[t + s]);
        __syncthreads();
    }
    if (t == 0) M = sred[0];
    __syncthreads();
    // per-partial scale factor and total l
    if (t < NPART) {
        float f = __expf(g_pm[b * NPART + t] - M);
        sw[t] = f;
        sred[t] = g_pl[b * NPART + t] * f;
    }
    __syncthreads();
    for (int s = 64; s > 0; s >>= 1) {
        if (t < s) sred[t] += sred[t + s];
        __syncthreads();
    }
    if (t == 0) Linv = 1.0f / sred[0];
    __syncthreads();
    // weighted combine of 128 partial vectors
    float4 a = make_float4(0.f, 0.f, 0.f, 0.f);
    const float4* base = (const float4*)(g_pacc + (size_t)b * NPART * DD);
#pragma unroll 4
    for (int i = 0; i < NPART; i++) {
        float w = sw[i];
        float4 v = base[(size_t)i * (DD / 4) + t];
        a.x += w * v.x; a.y += w * v.y; a.z += w * v.z; a.w += w * v.w;
    }
    float li = Linv;
    ((float4*)(g_xw + b * DD))[t] = make_float4(a.x * li, a.y * li, a.z * li, a.w * li);
}

// ---------------- K5: tmp[b] = Wv @ xw[b] + bv + xlast[b]  (grid = D) ----------------
__global__ void k_v(const float* __restrict__ emb, const float* __restrict__ Wv,
                    const float* __restrict__ bv) {
    int d = blockIdx.x, t = threadIdx.x;
    float4 w4 = ((const float4*)(Wv + (size_t)d * DD))[t];
    float acc[BB];
#pragma unroll
    for (int b = 0; b < BB; b++) {
        float4 x = ((const float4*)(g_xw + b * DD))[t];
        acc[b] = w4.x * x.x + w4.y * x.y + w4.z * x.z + w4.w * x.w;
    }
    __shared__ float red[BB][9];
    int lane = t & 31, wid = t >> 5;
#pragma unroll
    for (int b = 0; b < BB; b++) {
        float r = warp_sum(acc[b]);
        if (lane == 0) red[b][wid] = r;
    }
    __syncthreads();
    if (t < BB) {
        float s = 0.f;
#pragma unroll
        for (int w = 0; w < 8; w++) s += red[t][w];
        int row = g_tok[(t + 1) * TT - 1];
        g_tmp[t * DD + d] = s + bv[d] + emb[(size_t)row * DD + d];
    }
}

// ---------------- K6: inv1[b] = 1/max(||tmp[b]||, eps) ----------------
__global__ void k_norm1() {
    int b = blockIdx.x, t = threadIdx.x;
    float4 v = ((const float4*)(g_tmp + b * DD))[t];
    float ss = v.x * v.x + v.y * v.y + v.z * v.z + v.w * v.w;
    __shared__ float sh[256];
    sh[t] = ss; __syncthreads();
    for (int s = 128; s > 0; s >>= 1) { if (t < s) sh[t] += sh[t + s]; __syncthreads(); }
    if (t == 0) g_inv1[b] = 1.0f / fmaxf(sqrtf(sh[0]), 1e-12f);
}

// ---------------- K7: tmp2[b] = y + Wfc @ y + bfc,  y = tmp[b]*inv1[b] ----------------
__global__ void k_fc(const float* __restrict__ Wfc, const float* __restrict__ bfc) {
    int d = blockIdx.x, t = threadIdx.x;
    float4 w4 = ((const float4*)(Wfc + (size_t)d * DD))[t];
    float acc[BB];
#pragma unroll
    for (int b = 0; b < BB; b++) {
        float4 x = ((const float4*)(g_tmp + b * DD))[t];
        acc[b] = w4.x * x.x + w4.y * x.y + w4.z * x.z + w4.w * x.w;
    }
    __shared__ float red[BB][9];
    int lane = t & 31, wid = t >> 5;
#pragma unroll
    for (int b = 0; b < BB; b++) {
        float r = warp_sum(acc[b]);
        if (lane == 0) red[b][wid] = r;
    }
    __syncthreads();
    if (t < BB) {
        float s = 0.f;
#pragma unroll
        for (int w = 0; w < 8; w++) s += red[t][w];
        float inv = g_inv1[t];
        g_tmp2[t * DD + d] = (g_tmp[t * DD + d] + s) * inv + bfc[d];
    }
}

// ---------------- K8: l2norm + sigmoid(Wo @ z + bo) ----------------
__global__ void k_out(const float* __restrict__ Wo, const float* __restrict__ bo,
                      float* __restrict__ out) {
    int b = blockIdx.x, t = threadIdx.x;
    float4 v = ((const float4*)(g_tmp2 + b * DD))[t];
    float ss = v.x * v.x + v.y * v.y + v.z * v.z + v.w * v.w;
    __shared__ float sh[256];
    __shared__ float inv2;
    sh[t] = ss; __syncthreads();
    for (int s = 128; s > 0; s >>= 1) { if (t < s) sh[t] += sh[t + s]; __syncthreads(); }
    if (t == 0) inv2 = 1.0f / fmaxf(sqrtf(sh[0]), 1e-12f);
    __syncthreads();
    int wid = t >> 5, lane = t & 31;
    if (wid < CC) {
        float a = 0.f;
        for (int k = lane; k < DD; k += 32)
            a += Wo[wid * DD + k] * g_tmp2[b * DD + k];
        a = warp_sum(a);
        if (lane == 0) {
            float logit = a * inv2 + bo[wid];
            out[b * CC + wid] = 1.0f / (1.0f + expf(-logit));
        }
    }
}

// ---------------- launch ----------------
extern "C" void kernel_launch(void* const* d_in, const int* in_sizes, int n_in,
                              void* d_out, int out_size) {
    const void*  text = d_in[0];
    const float* emb  = (const float*)d_in[2];
    const float* Wq   = (const float*)d_in[3];
    const float* bq   = (const float*)d_in[4];
    const float* Wk   = (const float*)d_in[5];
    const float* Wv   = (const float*)d_in[7];
    const float* bv   = (const float*)d_in[8];
    const float* Wfc  = (const float*)d_in[9];
    const float* bfc  = (const float*)d_in[10];
    const float* Wo   = (const float*)d_in[11];
    const float* bo   = (const float*)d_in[12];
    int V = in_sizes[2] / DD;

    k_detect<<<1, 256>>>((const int2*)text, V);
    k_convert<<<(BB * TT + 255) / 256, 256>>>(text);
    k_q<<<DD, 256>>>(emb, Wq, bq);
    dim3 gqk(4, 32);
    k_qk<<<gqk, 256>>>(Wk);
    dim3 gat(NPART / 8, BB);
    k_attn<<<gat, 256>>>(emb, 1.0f / 32.0f);
    k_attn2<<<BB, 256>>>();
    k_v<<<DD, 256>>>(emb, Wv, bv);
    k_norm1<<<BB, 256>>>();
    k_fc<<<DD, 256>>>(Wfc, bfc);
    k_out<<<BB, 256>>>(Wo, bo, (float*)d_out);
}

// round 4
// speedup vs baseline: 1.5085x; 1.0368x over previous
#include <cuda_runtime.h>
#include <math.h>

#define BB 16
#define TT 2048
#define DD 1024
#define CC 6
#define NPART 128   // partials per batch in fused attention

// ---------------- device scratch (no allocs allowed) ----------------
__device__ int   g_is64;
__device__ int   g_tok[BB * TT];
__device__ float g_q[BB * DD];
__device__ float g_qk[BB * DD];
__device__ float g_xw[BB * DD];
__device__ float g_tmp[BB * DD];
__device__ float g_tmp2[BB * DD];
__device__ float g_pm[BB * NPART];
__device__ float g_pl[BB * NPART];
__device__ float g_pacc[BB * NPART * DD];   // 8 MB partial weighted sums

__device__ __forceinline__ float warp_sum(float v) {
#pragma unroll
    for (int o = 16; o > 0; o >>= 1) v += __shfl_down_sync(0xffffffffu, v, o);
    return v;
}
__device__ __forceinline__ float warp_allsum(float v) {
#pragma unroll
    for (int o = 16; o > 0; o >>= 1) v += __shfl_xor_sync(0xffffffffu, v, o);
    return v;
}

// ---------------- K0: detect int32 vs int64 token layout ----------------
__global__ void k_detect(const int2* text2, int V) {
    __shared__ int ok;
    if (threadIdx.x == 0) ok = 1;
    __syncthreads();
    for (int i = threadIdx.x; i < 4096; i += blockDim.x) {
        int2 v = text2[i];
        if (v.y != 0 || v.x < 0 || v.x >= V) ok = 0;
    }
    __syncthreads();
    if (threadIdx.x == 0) g_is64 = ok;
}

// ---------------- K1: convert tokens; zero g_qk ----------------
__global__ void k_convert(const void* text) {
    int i = blockIdx.x * blockDim.x + threadIdx.x;
    if (i < BB * TT) {
        int t;
        if (g_is64) t = (int)((const long long*)text)[i];
        else        t = ((const int*)text)[i];
        g_tok[i] = t;
    }
    if (i < BB * DD) g_qk[i] = 0.0f;
}

// ---------------- K2a: q[b] = Wq @ xlast[b] + bq  (grid = D) ----------------
__global__ void k_q(const float* __restrict__ emb, const float* __restrict__ Wq,
                    const float* __restrict__ bq) {
    int d = blockIdx.x, t = threadIdx.x;        // 256 threads
    float4 w4 = ((const float4*)(Wq + (size_t)d * DD))[t];
    float acc[BB];
#pragma unroll
    for (int b = 0; b < BB; b++) {
        int row = g_tok[(b + 1) * TT - 1];
        float4 x = ((const float4*)(emb + (size_t)row * DD))[t];
        acc[b] = w4.x * x.x + w4.y * x.y + w4.z * x.z + w4.w * x.w;
    }
    __shared__ float red[BB][9];
    int lane = t & 31, wid = t >> 5;
#pragma unroll
    for (int b = 0; b < BB; b++) {
        float r = warp_sum(acc[b]);
        if (lane == 0) red[b][wid] = r;
    }
    __syncthreads();
    if (t < BB) {
        float s = 0.f;
#pragma unroll
        for (int w = 0; w < 8; w++) s += red[t][w];
        g_q[t * DD + d] = s + bq[d];
    }
}

// ---------------- K2b: qk[b][j] += sum_d q[b][d] * Wk[d][j]  (grid (4,128)) ----------------
__global__ void k_qk(const float* __restrict__ Wk) {
    int j  = blockIdx.x * 256 + threadIdx.x;
    int d0 = blockIdx.y * 8;
    __shared__ float shq[BB * 8];
    if (threadIdx.x < BB * 8) {
        int b = threadIdx.x >> 3, dd = threadIdx.x & 7;
        shq[threadIdx.x] = g_q[b * DD + d0 + dd];
    }
    __syncthreads();
    float w[8];
#pragma unroll
    for (int dd = 0; dd < 8; dd++)
        w[dd] = Wk[(size_t)(d0 + dd) * DD + j];
    float acc[BB];
#pragma unroll
    for (int b = 0; b < BB; b++) {
        float a = 0.f;
#pragma unroll
        for (int dd = 0; dd < 8; dd++) a += shq[b * 8 + dd] * w[dd];
        acc[b] = a;
    }
#pragma unroll
    for (int b = 0; b < BB; b++) atomicAdd(&g_qk[b * DD + j], acc[b]);
}

// ---------------- K3: fused scores+softmax+wsum, single pass over emb rows -----
// grid (NPART/4, BB), 128 threads (4 warps). Each warp = one partial (16 tokens).
__global__ void __launch_bounds__(128) k_attn(const float* __restrict__ emb, float scale) {
    int b = blockIdx.y;
    int wid = threadIdx.x >> 5, lane = threadIdx.x & 31;
    int p = blockIdx.x * 4 + wid;               // partial index 0..127
    __shared__ float4 shqk[256];
    for (int i = threadIdx.x; i < 256; i += 128)
        shqk[i] = ((const float4*)(g_qk + b * DD))[i];
    __syncthreads();
    float4 qv[8];
#pragma unroll
    for (int it = 0; it < 8; it++) qv[it] = shqk[it * 32 + lane];

    int j0 = b * TT + p * 16;
    int rows[16];
#pragma unroll
    for (int jj = 0; jj < 16; jj++) rows[jj] = g_tok[j0 + jj];

    float m = -1e30f, l = 0.f;
    float4 acc[8];
#pragma unroll
    for (int it = 0; it < 8; it++) acc[it] = make_float4(0.f, 0.f, 0.f, 0.f);

#pragma unroll 2
    for (int jj = 0; jj < 16; jj++) {
        const float4* e4 = (const float4*)(emb + (size_t)rows[jj] * DD);
        float4 e[8];
#pragma unroll
        for (int it = 0; it < 8; it++) e[it] = e4[it * 32 + lane];
        float dot = 0.f;
#pragma unroll
        for (int it = 0; it < 8; it++)
            dot += e[it].x * qv[it].x + e[it].y * qv[it].y
                 + e[it].z * qv[it].z + e[it].w * qv[it].w;
        dot = warp_allsum(dot);
        float s = dot * scale;
        if (s <= m) {                      // warp-uniform fast path: no rescale
            float pw = __expf(s - m);
            l += pw;
#pragma unroll
            for (int it = 0; it < 8; it++) {
                acc[it].x += pw * e[it].x; acc[it].y += pw * e[it].y;
                acc[it].z += pw * e[it].z; acc[it].w += pw * e[it].w;
            }
        } else {                           // new max: rescale accumulators
            float f = __expf(m - s);
            l = l * f + 1.0f;
#pragma unroll
            for (int it = 0; it < 8; it++) {
                acc[it].x = acc[it].x * f + e[it].x;
                acc[it].y = acc[it].y * f + e[it].y;
                acc[it].z = acc[it].z * f + e[it].z;
                acc[it].w = acc[it].w * f + e[it].w;
            }
            m = s;
        }
    }
    if (lane == 0) { g_pm[b * NPART + p] = m; g_pl[b * NPART + p] = l; }
    float4* pa = (float4*)(g_pacc + ((size_t)(b * NPART + p)) * DD);
#pragma unroll
    for (int it = 0; it < 8; it++) pa[it * 32 + lane] = acc[it];
}

// ---------------- K4: combine partials -> g_xw  (grid = BB, 1024 thr) ----------------
__global__ void k_attn2() {
    int b = blockIdx.x, t = threadIdx.x;       // 1024 threads
    __shared__ float sred[NPART];
    __shared__ float sw[NPART];
    __shared__ float M, Linv;
    __shared__ float4 s4[1024];
    if (t < NPART) sred[t] = g_pm[b * NPART + t];
    __syncthreads();
    for (int s = 64; s > 0; s >>= 1) {
        if (t < s) sred[t] = fmaxf(sred[t], sred[t + s]);
        __syncthreads();
    }
    if (t == 0) M = sred[0];
    __syncthreads();
    if (t < NPART) {
        float f = __expf(g_pm[b * NPART + t] - M);
        sw[t] = f;
        sred[t] = g_pl[b * NPART + t] * f;
    }
    __syncthreads();
    for (int s = 64; s > 0; s >>= 1) {
        if (t < s) sred[t] += sred[t + s];
        __syncthreads();
    }
    if (t == 0) Linv = 1.0f / sred[0];
    __syncthreads();
    // 4 groups of 256 threads; group g combines partials [g*32, g*32+32)
    int e = t & 255, g = t >> 8;
    float4 a = make_float4(0.f, 0.f, 0.f, 0.f);
    const float4* base = (const float4*)(g_pacc + (size_t)b * NPART * DD);
#pragma unroll 8
    for (int i = g * 32; i < g * 32 + 32; i++) {
        float w = sw[i];
        float4 v = base[(size_t)i * (DD / 4) + e];
        a.x += w * v.x; a.y += w * v.y; a.z += w * v.z; a.w += w * v.w;
    }
    s4[t] = a;
    __syncthreads();
    if (g == 0) {
        float4 v1 = s4[t + 256], v2 = s4[t + 512], v3 = s4[t + 768];
        a.x += v1.x + v2.x + v3.x;
        a.y += v1.y + v2.y + v3.y;
        a.z += v1.z + v2.z + v3.z;
        a.w += v1.w + v2.w + v3.w;
        float li = Linv;
        ((float4*)(g_xw + b * DD))[e] =
            make_float4(a.x * li, a.y * li, a.z * li, a.w * li);
    }
}

// ---------------- K5: tmp[b] = Wv @ xw[b] + bv + xlast[b]  (grid = D) ----------------
__global__ void k_v(const float* __restrict__ emb, const float* __restrict__ Wv,
                    const float* __restrict__ bv) {
    int d = blockIdx.x, t = threadIdx.x;
    float4 w4 = ((const float4*)(Wv + (size_t)d * DD))[t];
    float acc[BB];
#pragma unroll
    for (int b = 0; b < BB; b++) {
        float4 x = ((const float4*)(g_xw + b * DD))[t];
        acc[b] = w4.x * x.x + w4.y * x.y + w4.z * x.z + w4.w * x.w;
    }
    __shared__ float red[BB][9];
    int lane = t & 31, wid = t >> 5;
#pragma unroll
    for (int b = 0; b < BB; b++) {
        float r = warp_sum(acc[b]);
        if (lane == 0) red[b][wid] = r;
    }
    __syncthreads();
    if (t < BB) {
        float s = 0.f;
#pragma unroll
        for (int w = 0; w < 8; w++) s += red[t][w];
        int row = g_tok[(t + 1) * TT - 1];
        g_tmp[t * DD + d] = s + bv[d] + emb[(size_t)row * DD + d];
    }
}

// ---------------- K6: tmp2[b] = y + Wfc @ y + bfc, y = tmp[b]/||tmp[b]|| -------
// norm computed in-kernel (redundantly per block, same reduction as the dot)
__global__ void k_fc(const float* __restrict__ Wfc, const float* __restrict__ bfc) {
    int d = blockIdx.x, t = threadIdx.x;
    float4 w4 = ((const float4*)(Wfc + (size_t)d * DD))[t];
    float acc[BB], ssq[BB];
#pragma unroll
    for (int b = 0; b < BB; b++) {
        float4 x = ((const float4*)(g_tmp + b * DD))[t];
        acc[b] = w4.x * x.x + w4.y * x.y + w4.z * x.z + w4.w * x.w;
        ssq[b] = x.x * x.x + x.y * x.y + x.z * x.z + x.w * x.w;
    }
    __shared__ float red[BB][9];
    __shared__ float red2[BB][9];
    int lane = t & 31, wid = t >> 5;
#pragma unroll
    for (int b = 0; b < BB; b++) {
        float r = warp_sum(acc[b]);
        float r2 = warp_sum(ssq[b]);
        if (lane == 0) { red[b][wid] = r; red2[b][wid] = r2; }
    }
    __syncthreads();
    if (t < BB) {
        float s = 0.f, ss = 0.f;
#pragma unroll
        for (int w = 0; w < 8; w++) { s += red[t][w]; ss += red2[t][w]; }
        float inv = 1.0f / fmaxf(sqrtf(ss), 1e-12f);
        g_tmp2[t * DD + d] = (g_tmp[t * DD + d] + s) * inv + bfc[d];
    }
}

// ---------------- K7: l2norm + sigmoid(Wo @ z + bo) ----------------
__global__ void k_out(const float* __restrict__ Wo, const float* __restrict__ bo,
                      float* __restrict__ out) {
    int b = blockIdx.x, t = threadIdx.x;
    float4 v = ((const float4*)(g_tmp2 + b * DD))[t];
    float ss = v.x * v.x + v.y * v.y + v.z * v.z + v.w * v.w;
    __shared__ float sh[256];
    __shared__ float inv2;
    sh[t] = ss; __syncthreads();
    for (int s = 128; s > 0; s >>= 1) { if (t < s) sh[t] += sh[t + s]; __syncthreads(); }
    if (t == 0) inv2 = 1.0f / fmaxf(sqrtf(sh[0]), 1e-12f);
    __syncthreads();
    int wid = t >> 5, lane = t & 31;
    if (wid < CC) {
        float a = 0.f;
        for (int k = lane; k < DD; k += 32)
            a += Wo[wid * DD + k] * g_tmp2[b * DD + k];
        a = warp_sum(a);
        if (lane == 0) {
            float logit = a * inv2 + bo[wid];
            out[b * CC + wid] = 1.0f / (1.0f + expf(-logit));
        }
    }
}

// ---------------- launch ----------------
extern "C" void kernel_launch(void* const* d_in, const int* in_sizes, int n_in,
                              void* d_out, int out_size) {
    const void*  text = d_in[0];
    const float* emb  = (const float*)d_in[2];
    const float* Wq   = (const float*)d_in[3];
    const float* bq   = (const float*)d_in[4];
    const float* Wk   = (const float*)d_in[5];
    const float* Wv   = (const float*)d_in[7];
    const float* bv   = (const float*)d_in[8];
    const float* Wfc  = (const float*)d_in[9];
    const float* bfc  = (const float*)d_in[10];
    const float* Wo   = (const float*)d_in[11];
    const float* bo   = (const float*)d_in[12];
    int V = in_sizes[2] / DD;

    k_detect<<<1, 256>>>((const int2*)text, V);
    k_convert<<<(BB * TT + 255) / 256, 256>>>(text);
    k_q<<<DD, 256>>>(emb, Wq, bq);
    dim3 gqk(4, 128);
    k_qk<<<gqk, 256>>>(Wk);
    dim3 gat(NPART / 4, BB);
    k_attn<<<gat, 128>>>(emb, 1.0f / 32.0f);
    k_attn2<<<BB, 1024>>>();
    k_v<<<DD, 256>>>(emb, Wv, bv);
    k_fc<<<DD, 256>>>(Wfc, bfc);
    k_out<<<BB, 256>>>(Wo, bo, (float*)d_out);
}